// round 11
// baseline (speedup 1.0000x reference)
#include <cuda_runtime.h>
#include <cstdint>

// Shapes (fixed)
#define B_    64
#define S_    16
#define J_    256
#define QDIM_ 512
#define IDIM_ 512
#define HDIM_ 256
#define BS_   (B_ * S_)      // 1024
#define CHK_  8              // rows per staged chunk
#define NCHK2_ (2 * J_ / CHK_)  // 64 chunks across the bs-pair

// Scratch (__device__ globals; 16B-aligned: accessed as float4/float2)
__device__ __align__(16) float g_Q[B_ * HDIM_];        // Wq q               [64, 256]
__device__ __align__(16) float g_qt[B_ * IDIM_];       // scale*Wk^T(Wq q)   [64, 512]
__device__ __align__(16) float g_pooled[BS_ * IDIM_];  // pooled inputs      [1024, 512]
__device__ __align__(16) float g_WvT[IDIM_ * HDIM_];   // Wv^T               [512, 256]
__device__ int g_mask_u8;                              // 1 = u8 bool mask, 0 = int32

// ---------------- cp.async helpers ----------------
__device__ __forceinline__ void cp_async16(unsigned dst_smem, const void* src) {
    asm volatile("cp.async.cg.shared.global [%0], [%1], 16;"
                 :: "r"(dst_smem), "l"(src));
}
__device__ __forceinline__ void cp_commit() {
    asm volatile("cp.async.commit_group;");
}
__device__ __forceinline__ void cp_wait0() {
    asm volatile("cp.async.wait_group 0;");
}
__device__ __forceinline__ void cp_wait1() {
    asm volatile("cp.async.wait_group 1;");
}

// ---------------------------------------------------------------------------
// Kernel 1 (prologue), grid = 192, block = 256:
//   blocks 0..127  : transpose Wv -> g_WvT (block 0 also detects mask dtype)
//   blocks 128..191: Q[b,h] (warp-per-2h, coalesced Wq reads + warp reduce)
// ---------------------------------------------------------------------------
__global__ __launch_bounds__(256) void prologue_kernel(
    const float*    __restrict__ query,  // [64, 512]
    const float*    __restrict__ Wq,     // [256, 512]
    const float*    __restrict__ Wv,     // [256, 512]
    const unsigned* __restrict__ mask_words)
{
    const int bx  = blockIdx.x;
    const int tid = threadIdx.x;

    if (bx < 128) {
        if (bx == 0) {   // mask dtype detection
            __shared__ int flag;
            if (tid == 0) flag = 0;
            __syncthreads();
            int loc = 0;
            #pragma unroll
            for (int k = 0; k < 4; ++k)
                if (mask_words[tid + 256 * k] > 1u) loc = 1;
            if (loc) flag = 1;
            __syncthreads();
            if (tid == 0) g_mask_u8 = flag;
        }
        __shared__ __align__(16) float tile[32][33];
        const int i0 = (bx & 15) * 32;
        const int h0 = (bx >> 4) * 32;
        const int tx = tid & 31;
        const int ty = tid >> 5;
        #pragma unroll
        for (int r = 0; r < 32; r += 8)
            tile[ty + r][tx] = Wv[(size_t)(h0 + ty + r) * IDIM_ + i0 + tx];
        __syncthreads();
        #pragma unroll
        for (int r = 0; r < 32; r += 8)
            g_WvT[(size_t)(i0 + ty + r) * HDIM_ + h0 + tx] = tile[tx][ty + r];
    } else {
        const int b    = bx - 128;
        const int wid  = tid >> 5;
        const int lane = tid & 31;

        __shared__ __align__(16) float sq[QDIM_];
        sq[tid]       = query[b * QDIM_ + tid];
        sq[tid + 256] = query[b * QDIM_ + tid + 256];
        __syncthreads();

        float4 qr[4];
        {
            const float4* q4 = reinterpret_cast<const float4*>(sq);
            #pragma unroll
            for (int k = 0; k < 4; ++k) qr[k] = q4[lane + 32 * k];
        }

        #pragma unroll 2
        for (int t = 0; t < 32; t += 2) {
            const int h = wid * 32 + t;
            const float4* w0 = reinterpret_cast<const float4*>(Wq + (size_t)h * QDIM_);
            const float4* w1 = reinterpret_cast<const float4*>(Wq + (size_t)(h + 1) * QDIM_);
            float s0 = 0.f, s1 = 0.f;
            #pragma unroll
            for (int k = 0; k < 4; ++k) {
                const float4 a = w0[lane + 32 * k];
                const float4 c = w1[lane + 32 * k];
                s0 = fmaf(a.x, qr[k].x, s0); s0 = fmaf(a.y, qr[k].y, s0);
                s0 = fmaf(a.z, qr[k].z, s0); s0 = fmaf(a.w, qr[k].w, s0);
                s1 = fmaf(c.x, qr[k].x, s1); s1 = fmaf(c.y, qr[k].y, s1);
                s1 = fmaf(c.z, qr[k].z, s1); s1 = fmaf(c.w, qr[k].w, s1);
            }
            #pragma unroll
            for (int off = 16; off > 0; off >>= 1) {
                s0 += __shfl_xor_sync(0xffffffffu, s0, off);
                s1 += __shfl_xor_sync(0xffffffffu, s1, off);
            }
            if (lane == 0) {
                g_Q[b * HDIM_ + h]     = s0;
                g_Q[b * HDIM_ + h + 1] = s1;
            }
        }
    }
}

// ---------------------------------------------------------------------------
// Kernel 1b: qt[b,i] = scale * sum_h Q[b,h] * Wk[h,i]
// grid = 256 (b x i-quarter); two threads per column, smem combine.
// ---------------------------------------------------------------------------
__global__ __launch_bounds__(256) void qt_kernel(
    const float* __restrict__ Wk)    // [256, 512]
{
    const int b    = blockIdx.x >> 2;
    const int i0   = (blockIdx.x & 3) * 128;
    const int tid  = threadIdx.x;
    const int col  = i0 + (tid & 127);
    const int hh   = tid >> 7;          // 0 or 1

    __shared__ __align__(16) float sQ[HDIM_];
    __shared__ float s_part[256];
    sQ[tid] = g_Q[b * HDIM_ + tid];
    __syncthreads();

    float a[8];
    #pragma unroll
    for (int k = 0; k < 8; ++k) a[k] = 0.f;

    const int hbase = hh * 128;
    #pragma unroll 4
    for (int h = 0; h < 128; h += 8) {
        #pragma unroll
        for (int k = 0; k < 8; ++k)
            a[k] = fmaf(sQ[hbase + h + k],
                        Wk[(size_t)(hbase + h + k) * IDIM_ + col], a[k]);
    }
    s_part[tid] = ((a[0] + a[1]) + (a[2] + a[3])) + ((a[4] + a[5]) + (a[6] + a[7]));
    __syncthreads();

    if (tid < 128) {
        const float scale = 0.0625f;  // 1/sqrt(256)
        g_qt[b * IDIM_ + i0 + tid] = (s_part[tid] + s_part[tid + 128]) * scale;
    }
}

// ---------------------------------------------------------------------------
// Kernel 2: flash softmax-pooling, PAIRED: one block handles bs=2k and 2k+1
// (same b, contiguous X, contiguous mask). 64-chunk uninterrupted cp.async
// pipeline; softmax state flushed/reset at the midpoint. grid=512 (1 wave).
// ---------------------------------------------------------------------------
__global__ __launch_bounds__(256, 4) void flash_pool_kernel(
    const float* __restrict__ X,     // [64,16,256,512]
    const void*  __restrict__ mask)  // [64,16,256] u8 or i32
{
    const int bs0  = blockIdx.x * 2;
    const int b    = bs0 >> 4;
    const int tid  = threadIdx.x;
    const int wid  = tid >> 5;
    const int lane = tid & 31;

    __shared__ __align__(16) float4 s_stage[3][CHK_ * 128];  // 3 x 16 KB
    __shared__ float s_score[CHK_];

    const float4* x4 = reinterpret_cast<const float4*>(X + (size_t)bs0 * J_ * IDIM_);
    const int mask_is_u8 = g_mask_u8;
    const uint8_t* mk8  = (const uint8_t*)mask + (size_t)bs0 * J_;   // 512 entries
    const int*     mk32 = (const int*)mask + (size_t)bs0 * J_;

    float4 qv[4];
    {
        const float4* q4 = reinterpret_cast<const float4*>(g_qt + b * IDIM_);
        #pragma unroll
        for (int k = 0; k < 4; ++k) qv[k] = q4[lane + 32 * k];
    }

    const unsigned sbase = (unsigned)__cvta_generic_to_shared(&s_stage[0][0]);
    const unsigned BUFB  = (unsigned)(CHK_ * 128 * 16);

    #pragma unroll
    for (int u = 0; u < 4; ++u)
        cp_async16(sbase + (unsigned)(tid + 256 * u) * 16u, x4 + tid + 256 * u);
    cp_commit();
    #pragma unroll
    for (int u = 0; u < 4; ++u)
        cp_async16(sbase + BUFB + (unsigned)(tid + 256 * u) * 16u,
                   x4 + CHK_ * 128 + tid + 256 * u);
    cp_commit();

    float m = -1e30f, d = 0.f;
    float px = 0.f, py = 0.f;
    int cur = 0, nxt2 = 2;

    for (int c = 0; c < NCHK2_; ++c) {
        if (c == NCHK2_ - 1) cp_wait0(); else cp_wait1();
        __syncthreads();

        if (c + 2 < NCHK2_) {
            const unsigned sb = sbase + (unsigned)nxt2 * BUFB;
            const float4* src = x4 + (size_t)(c + 2) * (CHK_ * 128);
            #pragma unroll
            for (int u = 0; u < 4; ++u)
                cp_async16(sb + (unsigned)(tid + 256 * u) * 16u, src + tid + 256 * u);
            cp_commit();
        }

        // Scores: warp w computes row w of this chunk
        {
            const float4* r0 = &s_stage[cur][wid * 128];
            float s0 = 0.f;
            #pragma unroll
            for (int k = 0; k < 4; ++k) {
                const float4 a = r0[lane + 32 * k];
                s0 = fmaf(a.x, qv[k].x, s0);
                s0 = fmaf(a.y, qv[k].y, s0);
                s0 = fmaf(a.z, qv[k].z, s0);
                s0 = fmaf(a.w, qv[k].w, s0);
            }
            #pragma unroll
            for (int off = 16; off > 0; off >>= 1)
                s0 += __shfl_xor_sync(0xffffffffu, s0, off);
            if (lane == 0) s_score[wid] = s0;
        }
        __syncthreads();

        // Softmax coefficients (redundant per-warp, identical results)
        float sc = -1e30f;
        if (lane < CHK_) {
            sc = s_score[lane];
            const int j = c * CHK_ + lane;   // global row in [0, 512)
            const bool msk = mask_is_u8 ? (mk8[j] != 0) : (mk32[j] != 0);
            if (msk) sc = -1e30f;
        }
        float mx = sc;
        #pragma unroll
        for (int off = 16; off > 0; off >>= 1)
            mx = fmaxf(mx, __shfl_xor_sync(0xffffffffu, mx, off));
        const float Mn = fmaxf(m, mx);
        const float w  = (lane < CHK_) ? __expf(sc - Mn) : 0.f;
        float ws = w;
        #pragma unroll
        for (int off = 16; off > 0; off >>= 1)
            ws += __shfl_xor_sync(0xffffffffu, ws, off);
        const float f = __expf(m - Mn);
        m = Mn;
        d = fmaf(d, f, ws);

        // Accumulate: thread owns cols {2*tid, 2*tid+1}
        px *= f;  py *= f;
        const float2* st2 = reinterpret_cast<const float2*>(&s_stage[cur][0]);
        #pragma unroll
        for (int r = 0; r < CHK_; ++r) {
            const float  wr = __shfl_sync(0xffffffffu, w, r);
            const float2 xv = st2[r * 256 + tid];
            px = fmaf(wr, xv.x, px);
            py = fmaf(wr, xv.y, py);
        }

        // Midpoint flush: first bs of the pair is complete
        if (c == NCHK2_ / 2 - 1) {
            const float inv = 1.f / d;
            reinterpret_cast<float2*>(g_pooled + (size_t)bs0 * IDIM_)[tid] =
                make_float2(px * inv, py * inv);
            m = -1e30f;  d = 0.f;  px = 0.f;  py = 0.f;
        }

        cur  = (cur == 2)  ? 0 : cur + 1;
        nxt2 = (nxt2 == 2) ? 0 : nxt2 + 1;
    }

    const float inv = 1.f / d;
    reinterpret_cast<float2*>(g_pooled + (size_t)(bs0 + 1) * IDIM_)[tid] =
        make_float2(px * inv, py * inv);
}

// ---------------------------------------------------------------------------
// Kernel 3: smem-tiled GEMM  out[1024,256] = pooled[1024,512] @ WvT[512,256]
// BM=16, BN=64, BK=32; 256 threads, 1x4 register tile; 256 blocks (~2/SM).
// ---------------------------------------------------------------------------
#define BM_ 16
#define BN_ 64
#define BK_ 32
__global__ __launch_bounds__(256) void epilogue_kernel(float* __restrict__ out)
{
    const int tid = threadIdx.x;
    const int h0  = blockIdx.x * BN_;   // 0..3
    const int m0  = blockIdx.y * BM_;   // 0..63
    const int tx  = tid & 15;           // n-quad
    const int my  = tid >> 4;           // m-row 0..15

    __shared__ float sA[BM_][BK_ + 1];              // 2.1 KB, padded
    __shared__ __align__(16) float sB[BK_][BN_];    // 8 KB

    float4 acc = make_float4(0.f, 0.f, 0.f, 0.f);

    const int ar = tid >> 3;          // 0..31 (only <16 valid)
    const int ac = (tid & 7) * 4;     // k col (float4)
    const int br = tid >> 4;          // 0..15 (k row)
    const int bc = (tid & 15) * 4;    // n col (float4)

    for (int k0 = 0; k0 < IDIM_; k0 += BK_) {
        if (ar < BM_) {   // A tile 16x32: 128 float4, threads 0..127
            const float4 v = *reinterpret_cast<const float4*>(
                g_pooled + (size_t)(m0 + ar) * IDIM_ + k0 + ac);
            sA[ar][ac + 0] = v.x;  sA[ar][ac + 1] = v.y;
            sA[ar][ac + 2] = v.z;  sA[ar][ac + 3] = v.w;
        }
        #pragma unroll
        for (int r = 0; r < 2; ++r) {   // B tile 32x64: 2 float4/thread
            const int kk = br + 16 * r;
            *reinterpret_cast<float4*>(&sB[kk][bc]) =
                *reinterpret_cast<const float4*>(
                    g_WvT + (size_t)(k0 + kk) * HDIM_ + h0 + bc);
        }
        __syncthreads();

        #pragma unroll
        for (int kk = 0; kk < BK_; ++kk) {
            const float  a  = sA[my][kk];
            const float4 bv = *reinterpret_cast<const float4*>(&sB[kk][tx * 4]);
            acc.x = fmaf(a, bv.x, acc.x);
            acc.y = fmaf(a, bv.y, acc.y);
            acc.z = fmaf(a, bv.z, acc.z);
            acc.w = fmaf(a, bv.w, acc.w);
        }
        __syncthreads();
    }

    *reinterpret_cast<float4*>(
        out + (size_t)(m0 + my) * HDIM_ + h0 + tx * 4) = acc;
}

// ---------------------------------------------------------------------------
// Launch.  Inputs: query, other_semesters, mask, Wq, Wk, Wv
// ---------------------------------------------------------------------------
extern "C" void kernel_launch(void* const* d_in, const int* in_sizes, int n_in,
                              void* d_out, int out_size)
{
    const float* query = (const float*)d_in[0];
    const float* X     = (const float*)d_in[1];
    const void*  mask  = d_in[2];
    const float* Wq    = (const float*)d_in[3];
    const float* Wk    = (const float*)d_in[4];
    const float* Wv    = (const float*)d_in[5];
    float*       out   = (float*)d_out;

    prologue_kernel<<<192, 256>>>(query, Wq, Wv, (const unsigned*)mask);
    qt_kernel<<<256, 256>>>(Wk);
    flash_pool_kernel<<<BS_ / 2, 256>>>(X, mask);
    epilogue_kernel<<<dim3(HDIM_ / BN_, BS_ / BM_), 256>>>(out);
}

// round 12
// speedup vs baseline: 1.1207x; 1.1207x over previous
#include <cuda_runtime.h>
#include <cstdint>

// Shapes (fixed)
#define B_    64
#define S_    16
#define J_    256
#define QDIM_ 512
#define IDIM_ 512
#define HDIM_ 256
#define BS_   (B_ * S_)    // 1024
#define CHK_  8            // rows per staged chunk
#define NCHK_ (J_ / CHK_)  // 32 chunks

// Scratch (__device__ globals; 16B-aligned: accessed as float4/float2)
__device__ __align__(16) float g_Q[B_ * HDIM_];        // Wq q               [64, 256]
__device__ __align__(16) float g_qt[B_ * IDIM_];       // scale*Wk^T(Wq q)   [64, 512]
__device__ __align__(16) float g_pooled[BS_ * IDIM_];  // pooled inputs      [1024, 512]
__device__ __align__(16) float g_WvT[IDIM_ * HDIM_];   // Wv^T               [512, 256]
__device__ int g_mask_u8;                              // 1 = u8 bool mask, 0 = int32

// ---------------- cp.async helpers ----------------
__device__ __forceinline__ void cp_async16(unsigned dst_smem, const void* src) {
    asm volatile("cp.async.cg.shared.global [%0], [%1], 16;"
                 :: "r"(dst_smem), "l"(src));
}
__device__ __forceinline__ void cp_commit() {
    asm volatile("cp.async.commit_group;");
}
__device__ __forceinline__ void cp_wait0() {
    asm volatile("cp.async.wait_group 0;");
}
__device__ __forceinline__ void cp_wait1() {
    asm volatile("cp.async.wait_group 1;");
}

// ---------------------------------------------------------------------------
// Kernel 1 (prologue), grid = 192, block = 256:  (identical to R10)
//   blocks 0..127  : transpose Wv -> g_WvT (block 0 also detects mask dtype)
//   blocks 128..191: Q[b,h] (warp-per-2h, coalesced Wq reads + warp reduce)
// ---------------------------------------------------------------------------
__global__ __launch_bounds__(256) void prologue_kernel(
    const float*    __restrict__ query,  // [64, 512]
    const float*    __restrict__ Wq,     // [256, 512]
    const float*    __restrict__ Wv,     // [256, 512]
    const unsigned* __restrict__ mask_words)
{
    const int bx  = blockIdx.x;
    const int tid = threadIdx.x;

    if (bx < 128) {
        if (bx == 0) {   // mask dtype detection
            __shared__ int flag;
            if (tid == 0) flag = 0;
            __syncthreads();
            int loc = 0;
            #pragma unroll
            for (int k = 0; k < 4; ++k)
                if (mask_words[tid + 256 * k] > 1u) loc = 1;
            if (loc) flag = 1;
            __syncthreads();
            if (tid == 0) g_mask_u8 = flag;
        }
        __shared__ __align__(16) float tile[32][33];
        const int i0 = (bx & 15) * 32;
        const int h0 = (bx >> 4) * 32;
        const int tx = tid & 31;
        const int ty = tid >> 5;
        #pragma unroll
        for (int r = 0; r < 32; r += 8)
            tile[ty + r][tx] = Wv[(size_t)(h0 + ty + r) * IDIM_ + i0 + tx];
        __syncthreads();
        #pragma unroll
        for (int r = 0; r < 32; r += 8)
            g_WvT[(size_t)(i0 + ty + r) * HDIM_ + h0 + tx] = tile[tx][ty + r];
    } else {
        const int b    = bx - 128;
        const int wid  = tid >> 5;
        const int lane = tid & 31;

        __shared__ __align__(16) float sq[QDIM_];
        sq[tid]       = query[b * QDIM_ + tid];
        sq[tid + 256] = query[b * QDIM_ + tid + 256];
        __syncthreads();

        float4 qr[4];
        {
            const float4* q4 = reinterpret_cast<const float4*>(sq);
            #pragma unroll
            for (int k = 0; k < 4; ++k) qr[k] = q4[lane + 32 * k];
        }

        #pragma unroll 2
        for (int t = 0; t < 32; t += 2) {
            const int h = wid * 32 + t;
            const float4* w0 = reinterpret_cast<const float4*>(Wq + (size_t)h * QDIM_);
            const float4* w1 = reinterpret_cast<const float4*>(Wq + (size_t)(h + 1) * QDIM_);
            float s0 = 0.f, s1 = 0.f;
            #pragma unroll
            for (int k = 0; k < 4; ++k) {
                const float4 a = w0[lane + 32 * k];
                const float4 c = w1[lane + 32 * k];
                s0 = fmaf(a.x, qr[k].x, s0); s0 = fmaf(a.y, qr[k].y, s0);
                s0 = fmaf(a.z, qr[k].z, s0); s0 = fmaf(a.w, qr[k].w, s0);
                s1 = fmaf(c.x, qr[k].x, s1); s1 = fmaf(c.y, qr[k].y, s1);
                s1 = fmaf(c.z, qr[k].z, s1); s1 = fmaf(c.w, qr[k].w, s1);
            }
            #pragma unroll
            for (int off = 16; off > 0; off >>= 1) {
                s0 += __shfl_xor_sync(0xffffffffu, s0, off);
                s1 += __shfl_xor_sync(0xffffffffu, s1, off);
            }
            if (lane == 0) {
                g_Q[b * HDIM_ + h]     = s0;
                g_Q[b * HDIM_ + h + 1] = s1;
            }
        }
    }
}

// ---------------------------------------------------------------------------
// Kernel 1b: qt[b,i] = scale * sum_h Q[b,h] * Wk[h,i]   (identical to R10)
// grid = 256 (b x i-quarter); two threads per column, smem combine.
// ---------------------------------------------------------------------------
__global__ __launch_bounds__(256) void qt_kernel(
    const float* __restrict__ Wk)    // [256, 512]
{
    const int b    = blockIdx.x >> 2;
    const int i0   = (blockIdx.x & 3) * 128;
    const int tid  = threadIdx.x;
    const int col  = i0 + (tid & 127);
    const int hh   = tid >> 7;          // 0 or 1

    __shared__ __align__(16) float sQ[HDIM_];
    __shared__ float s_part[256];
    sQ[tid] = g_Q[b * HDIM_ + tid];
    __syncthreads();

    float a[8];
    #pragma unroll
    for (int k = 0; k < 8; ++k) a[k] = 0.f;

    const int hbase = hh * 128;
    #pragma unroll 4
    for (int h = 0; h < 128; h += 8) {
        #pragma unroll
        for (int k = 0; k < 8; ++k)
            a[k] = fmaf(sQ[hbase + h + k],
                        Wk[(size_t)(hbase + h + k) * IDIM_ + col], a[k]);
    }
    s_part[tid] = ((a[0] + a[1]) + (a[2] + a[3])) + ((a[4] + a[5]) + (a[6] + a[7]));
    __syncthreads();

    if (tid < 128) {
        const float scale = 0.0625f;  // 1/sqrt(256)
        g_qt[b * IDIM_ + i0 + tid] = (s_part[tid] + s_part[tid + 128]) * scale;
    }
}

// ---------------------------------------------------------------------------
// Kernel 2: chunked flash softmax-pooling, 3-stage cp.async pipeline.
// CHK=8 (3x16KB smem), 4 CTAs/SM. One block per (b,s).  (identical to R10)
// ---------------------------------------------------------------------------
__global__ __launch_bounds__(256, 4) void flash_pool_kernel(
    const float* __restrict__ X,     // [64,16,256,512]
    const void*  __restrict__ mask)  // [64,16,256] u8 or i32
{
    const int bs   = blockIdx.x;
    const int b    = bs >> 4;
    const int tid  = threadIdx.x;
    const int wid  = tid >> 5;
    const int lane = tid & 31;

    __shared__ __align__(16) float4 s_stage[3][CHK_ * 128];  // 3 x 16 KB
    __shared__ float s_score[CHK_];

    const float4* x4 = reinterpret_cast<const float4*>(X + (size_t)bs * J_ * IDIM_);
    const int mask_is_u8 = g_mask_u8;
    const uint8_t* mk8  = (const uint8_t*)mask + (size_t)bs * J_;
    const int*     mk32 = (const int*)mask + (size_t)bs * J_;

    float4 qv[4];
    {
        const float4* q4 = reinterpret_cast<const float4*>(g_qt + b * IDIM_);
        #pragma unroll
        for (int k = 0; k < 4; ++k) qv[k] = q4[lane + 32 * k];
    }

    const unsigned sbase = (unsigned)__cvta_generic_to_shared(&s_stage[0][0]);
    const unsigned BUFB  = (unsigned)(CHK_ * 128 * 16);

    #pragma unroll
    for (int u = 0; u < 4; ++u)
        cp_async16(sbase + (unsigned)(tid + 256 * u) * 16u, x4 + tid + 256 * u);
    cp_commit();
    #pragma unroll
    for (int u = 0; u < 4; ++u)
        cp_async16(sbase + BUFB + (unsigned)(tid + 256 * u) * 16u,
                   x4 + CHK_ * 128 + tid + 256 * u);
    cp_commit();

    float m = -1e30f, d = 0.f;
    float px = 0.f, py = 0.f;
    int cur = 0, nxt2 = 2;

    for (int c = 0; c < NCHK_; ++c) {
        if (c == NCHK_ - 1) cp_wait0(); else cp_wait1();
        __syncthreads();

        if (c + 2 < NCHK_) {
            const unsigned sb = sbase + (unsigned)nxt2 * BUFB;
            const float4* src = x4 + (size_t)(c + 2) * (CHK_ * 128);
            #pragma unroll
            for (int u = 0; u < 4; ++u)
                cp_async16(sb + (unsigned)(tid + 256 * u) * 16u, src + tid + 256 * u);
            cp_commit();
        }

        {
            const float4* r0 = &s_stage[cur][wid * 128];
            float s0 = 0.f;
            #pragma unroll
            for (int k = 0; k < 4; ++k) {
                const float4 a = r0[lane + 32 * k];
                s0 = fmaf(a.x, qv[k].x, s0);
                s0 = fmaf(a.y, qv[k].y, s0);
                s0 = fmaf(a.z, qv[k].z, s0);
                s0 = fmaf(a.w, qv[k].w, s0);
            }
            #pragma unroll
            for (int off = 16; off > 0; off >>= 1)
                s0 += __shfl_xor_sync(0xffffffffu, s0, off);
            if (lane == 0) s_score[wid] = s0;
        }
        __syncthreads();

        float sc = -1e30f;
        if (lane < CHK_) {
            sc = s_score[lane];
            const int j = c * CHK_ + lane;
            const bool msk = mask_is_u8 ? (mk8[j] != 0) : (mk32[j] != 0);
            if (msk) sc = -1e30f;
        }
        float mx = sc;
        #pragma unroll
        for (int off = 16; off > 0; off >>= 1)
            mx = fmaxf(mx, __shfl_xor_sync(0xffffffffu, mx, off));
        const float Mn = fmaxf(m, mx);
        const float w  = (lane < CHK_) ? __expf(sc - Mn) : 0.f;
        float ws = w;
        #pragma unroll
        for (int off = 16; off > 0; off >>= 1)
            ws += __shfl_xor_sync(0xffffffffu, ws, off);
        const float f = __expf(m - Mn);
        m = Mn;
        d = fmaf(d, f, ws);

        px *= f;  py *= f;
        const float2* st2 = reinterpret_cast<const float2*>(&s_stage[cur][0]);
        #pragma unroll
        for (int r = 0; r < CHK_; ++r) {
            const float  wr = __shfl_sync(0xffffffffu, w, r);
            const float2 xv = st2[r * 256 + tid];
            px = fmaf(wr, xv.x, px);
            py = fmaf(wr, xv.y, py);
        }

        cur  = (cur == 2)  ? 0 : cur + 1;
        nxt2 = (nxt2 == 2) ? 0 : nxt2 + 1;
    }

    const float inv = 1.f / d;
    reinterpret_cast<float2*>(g_pooled + (size_t)bs * IDIM_)[tid] =
        make_float2(px * inv, py * inv);
}

// ---------------------------------------------------------------------------
// Kernel 3: cp.async double-buffered GEMM
// out[1024,256] = pooled[1024,512] @ WvT[512,256]
// BM=32, BN=64, BK=32; 256 threads, 2x4 register tile; 128 blocks.
// sA padded to 36 floats/row (144 B) so cp.async 16B dsts stay aligned.
// ---------------------------------------------------------------------------
#define BM_ 32
#define BN_ 64
#define BK_ 32
#define SAP_ 36
__global__ __launch_bounds__(256) void epilogue_kernel(float* __restrict__ out)
{
    const int tid = threadIdx.x;
    const int h0  = blockIdx.x * BN_;
    const int m0  = blockIdx.y * BM_;
    const int tx  = tid & 15;
    const int ty  = tid >> 4;

    __shared__ __align__(16) float sA[2][BM_][SAP_];   // 2 x 4.5 KB
    __shared__ __align__(16) float sB[2][BK_][BN_];    // 2 x 8 KB

    float acc[2][4];
    #pragma unroll
    for (int i = 0; i < 2; ++i)
        #pragma unroll
        for (int j = 0; j < 4; ++j) acc[i][j] = 0.f;

    const int ar = tid >> 3;          // 0..31 (m row)
    const int ac = (tid & 7) * 4;     // k col (float4)
    const int br = tid >> 4;          // 0..15 (k row)
    const int bc = (tid & 15) * 4;    // n col (float4)

    const unsigned sAu = (unsigned)__cvta_generic_to_shared(&sA[0][0][0]);
    const unsigned sBu = (unsigned)__cvta_generic_to_shared(&sB[0][0][0]);
    const unsigned ABUF = (unsigned)(BM_ * SAP_ * 4);   // bytes per sA buffer
    const unsigned BBUF = (unsigned)(BK_ * BN_ * 4);    // bytes per sB buffer

    // Issue chunk 0 into buffer 0
    {
        cp_async16(sAu + (unsigned)(ar * SAP_ + ac) * 4u,
                   g_pooled + (size_t)(m0 + ar) * IDIM_ + ac);
        #pragma unroll
        for (int r = 0; r < 2; ++r) {
            const int kk = br + 16 * r;
            cp_async16(sBu + (unsigned)(kk * BN_ + bc) * 4u,
                       g_WvT + (size_t)kk * HDIM_ + h0 + bc);
        }
        cp_commit();
    }

    const int NCH = IDIM_ / BK_;   // 16
    for (int c = 0; c < NCH; ++c) {
        const int cur = c & 1;

        // Issue chunk c+1 into the other buffer (its compute finished last iter)
        if (c + 1 < NCH) {
            const int k0 = (c + 1) * BK_;
            const unsigned oa = sAu + (unsigned)(cur ^ 1) * ABUF;
            const unsigned ob = sBu + (unsigned)(cur ^ 1) * BBUF;
            cp_async16(oa + (unsigned)(ar * SAP_ + ac) * 4u,
                       g_pooled + (size_t)(m0 + ar) * IDIM_ + k0 + ac);
            #pragma unroll
            for (int r = 0; r < 2; ++r) {
                const int kk = br + 16 * r;
                cp_async16(ob + (unsigned)(kk * BN_ + bc) * 4u,
                           g_WvT + (size_t)(k0 + kk) * HDIM_ + h0 + bc);
            }
            cp_commit();
        }

        // Wait for chunk c (leave chunk c+1's group in flight)
        if (c + 1 < NCH) cp_wait1(); else cp_wait0();
        __syncthreads();

        #pragma unroll
        for (int kk = 0; kk < BK_; ++kk) {
            const float a0 = sA[cur][ty * 2 + 0][kk];
            const float a1 = sA[cur][ty * 2 + 1][kk];
            const float4 bv = *reinterpret_cast<const float4*>(&sB[cur][kk][tx * 4]);
            acc[0][0] = fmaf(a0, bv.x, acc[0][0]);
            acc[0][1] = fmaf(a0, bv.y, acc[0][1]);
            acc[0][2] = fmaf(a0, bv.z, acc[0][2]);
            acc[0][3] = fmaf(a0, bv.w, acc[0][3]);
            acc[1][0] = fmaf(a1, bv.x, acc[1][0]);
            acc[1][1] = fmaf(a1, bv.y, acc[1][1]);
            acc[1][2] = fmaf(a1, bv.z, acc[1][2]);
            acc[1][3] = fmaf(a1, bv.w, acc[1][3]);
        }
        __syncthreads();   // compute done before next issue overwrites this buffer
    }

    #pragma unroll
    for (int i = 0; i < 2; ++i) {
        const float4 v = make_float4(acc[i][0], acc[i][1], acc[i][2], acc[i][3]);
        *reinterpret_cast<float4*>(
            out + (size_t)(m0 + ty * 2 + i) * HDIM_ + h0 + tx * 4) = v;
    }
}

// ---------------------------------------------------------------------------
// Launch.  Inputs: query, other_semesters, mask, Wq, Wk, Wv
// ---------------------------------------------------------------------------
extern "C" void kernel_launch(void* const* d_in, const int* in_sizes, int n_in,
                              void* d_out, int out_size)
{
    const float* query = (const float*)d_in[0];
    const float* X     = (const float*)d_in[1];
    const void*  mask  = d_in[2];
    const float* Wq    = (const float*)d_in[3];
    const float* Wk    = (const float*)d_in[4];
    const float* Wv    = (const float*)d_in[5];
    float*       out   = (float*)d_out;

    prologue_kernel<<<192, 256>>>(query, Wq, Wv, (const unsigned*)mask);
    qt_kernel<<<256, 256>>>(Wk);
    flash_pool_kernel<<<BS_, 256>>>(X, mask);
    epilogue_kernel<<<dim3(HDIM_ / BN_, BS_ / BM_), 256>>>(out);
}

// round 13
// speedup vs baseline: 1.2778x; 1.1402x over previous
#include <cuda_runtime.h>
#include <cstdint>

// Shapes (fixed)
#define B_    64
#define S_    16
#define J_    256
#define QDIM_ 512
#define IDIM_ 512
#define HDIM_ 256
#define BS_   (B_ * S_)    // 1024
#define CHK_  8            // rows per staged chunk
#define NCHK_ (J_ / CHK_)  // 32 chunks

// Scratch (__device__ globals; 16B-aligned: accessed as float4/float2)
__device__ __align__(16) float g_Q[B_ * HDIM_];        // Wq q               [64, 256]
__device__ __align__(16) float g_qt[B_ * IDIM_];       // scale*Wk^T(Wq q)   [64, 512]
__device__ __align__(16) float g_pooled[BS_ * IDIM_];  // pooled inputs      [1024, 512]
__device__ __align__(16) float g_WvT[IDIM_ * HDIM_];   // Wv^T               [512, 256]
__device__ int g_mask_u8;                              // 1 = u8 bool mask, 0 = int32

// ---------------- cp.async helpers ----------------
__device__ __forceinline__ void cp_async16(unsigned dst_smem, const void* src) {
    asm volatile("cp.async.cg.shared.global [%0], [%1], 16;"
                 :: "r"(dst_smem), "l"(src));
}
__device__ __forceinline__ void cp_commit() {
    asm volatile("cp.async.commit_group;");
}
__device__ __forceinline__ void cp_wait0() {
    asm volatile("cp.async.wait_group 0;");
}
__device__ __forceinline__ void cp_wait1() {
    asm volatile("cp.async.wait_group 1;");
}

// ---------------------------------------------------------------------------
// Kernel 1 (prologue), grid = 192, block = 256:  (identical to R12)
// ---------------------------------------------------------------------------
__global__ __launch_bounds__(256) void prologue_kernel(
    const float*    __restrict__ query,  // [64, 512]
    const float*    __restrict__ Wq,     // [256, 512]
    const float*    __restrict__ Wv,     // [256, 512]
    const unsigned* __restrict__ mask_words)
{
    const int bx  = blockIdx.x;
    const int tid = threadIdx.x;

    if (bx < 128) {
        if (bx == 0) {   // mask dtype detection
            __shared__ int flag;
            if (tid == 0) flag = 0;
            __syncthreads();
            int loc = 0;
            #pragma unroll
            for (int k = 0; k < 4; ++k)
                if (mask_words[tid + 256 * k] > 1u) loc = 1;
            if (loc) flag = 1;
            __syncthreads();
            if (tid == 0) g_mask_u8 = flag;
        }
        __shared__ __align__(16) float tile[32][33];
        const int i0 = (bx & 15) * 32;
        const int h0 = (bx >> 4) * 32;
        const int tx = tid & 31;
        const int ty = tid >> 5;
        #pragma unroll
        for (int r = 0; r < 32; r += 8)
            tile[ty + r][tx] = Wv[(size_t)(h0 + ty + r) * IDIM_ + i0 + tx];
        __syncthreads();
        #pragma unroll
        for (int r = 0; r < 32; r += 8)
            g_WvT[(size_t)(i0 + ty + r) * HDIM_ + h0 + tx] = tile[tx][ty + r];
    } else {
        const int b    = bx - 128;
        const int wid  = tid >> 5;
        const int lane = tid & 31;

        __shared__ __align__(16) float sq[QDIM_];
        sq[tid]       = query[b * QDIM_ + tid];
        sq[tid + 256] = query[b * QDIM_ + tid + 256];
        __syncthreads();

        float4 qr[4];
        {
            const float4* q4 = reinterpret_cast<const float4*>(sq);
            #pragma unroll
            for (int k = 0; k < 4; ++k) qr[k] = q4[lane + 32 * k];
        }

        #pragma unroll 2
        for (int t = 0; t < 32; t += 2) {
            const int h = wid * 32 + t;
            const float4* w0 = reinterpret_cast<const float4*>(Wq + (size_t)h * QDIM_);
            const float4* w1 = reinterpret_cast<const float4*>(Wq + (size_t)(h + 1) * QDIM_);
            float s0 = 0.f, s1 = 0.f;
            #pragma unroll
            for (int k = 0; k < 4; ++k) {
                const float4 a = w0[lane + 32 * k];
                const float4 c = w1[lane + 32 * k];
                s0 = fmaf(a.x, qr[k].x, s0); s0 = fmaf(a.y, qr[k].y, s0);
                s0 = fmaf(a.z, qr[k].z, s0); s0 = fmaf(a.w, qr[k].w, s0);
                s1 = fmaf(c.x, qr[k].x, s1); s1 = fmaf(c.y, qr[k].y, s1);
                s1 = fmaf(c.z, qr[k].z, s1); s1 = fmaf(c.w, qr[k].w, s1);
            }
            #pragma unroll
            for (int off = 16; off > 0; off >>= 1) {
                s0 += __shfl_xor_sync(0xffffffffu, s0, off);
                s1 += __shfl_xor_sync(0xffffffffu, s1, off);
            }
            if (lane == 0) {
                g_Q[b * HDIM_ + h]     = s0;
                g_Q[b * HDIM_ + h + 1] = s1;
            }
        }
    }
}

// ---------------------------------------------------------------------------
// Kernel 1b: qt[b,i] = scale * sum_h Q[b,h] * Wk[h,i]   (identical to R12)
// ---------------------------------------------------------------------------
__global__ __launch_bounds__(256) void qt_kernel(
    const float* __restrict__ Wk)    // [256, 512]
{
    const int b    = blockIdx.x >> 2;
    const int i0   = (blockIdx.x & 3) * 128;
    const int tid  = threadIdx.x;
    const int col  = i0 + (tid & 127);
    const int hh   = tid >> 7;          // 0 or 1

    __shared__ __align__(16) float sQ[HDIM_];
    __shared__ float s_part[256];
    sQ[tid] = g_Q[b * HDIM_ + tid];
    __syncthreads();

    float a[8];
    #pragma unroll
    for (int k = 0; k < 8; ++k) a[k] = 0.f;

    const int hbase = hh * 128;
    #pragma unroll 4
    for (int h = 0; h < 128; h += 8) {
        #pragma unroll
        for (int k = 0; k < 8; ++k)
            a[k] = fmaf(sQ[hbase + h + k],
                        Wk[(size_t)(hbase + h + k) * IDIM_ + col], a[k]);
    }
    s_part[tid] = ((a[0] + a[1]) + (a[2] + a[3])) + ((a[4] + a[5]) + (a[6] + a[7]));
    __syncthreads();

    if (tid < 128) {
        const float scale = 0.0625f;  // 1/sqrt(256)
        g_qt[b * IDIM_ + i0 + tid] = (s_part[tid] + s_part[tid + 128]) * scale;
    }
}

// ---------------------------------------------------------------------------
// Kernel 2: flash softmax-pooling, PER-WARP-PRIVATE state.
// Warp w owns row w of each 8-row chunk: loads it ONCE (regs), uses it for
// both score and p-update. One barrier per chunk (buffer reuse). Mask is
// preloaded (1 byte/lane) and broadcast by shfl. End-merge via staging smem.
// 3-stage cp.async pipeline, 4 CTAs/SM.
// ---------------------------------------------------------------------------
__global__ __launch_bounds__(256, 4) void flash_pool_kernel(
    const float* __restrict__ X,     // [64,16,256,512]
    const void*  __restrict__ mask)  // [64,16,256] u8 or i32
{
    const int bs   = blockIdx.x;
    const int b    = bs >> 4;
    const int tid  = threadIdx.x;
    const int wid  = tid >> 5;
    const int lane = tid & 31;

    __shared__ __align__(16) float4 s_stage[3][CHK_ * 128];  // 3 x 16 KB (also merge buf)
    __shared__ float s_m[8], s_d[8];

    const float4* x4 = reinterpret_cast<const float4*>(X + (size_t)bs * J_ * IDIM_);

    // Preload mask: lane holds the bit for chunk 'lane' of this warp's rows
    // (row j = lane*8 + wid). Broadcast per chunk via shfl.
    int mval;
    {
        const int j = lane * CHK_ + wid;   // 0..255
        if (g_mask_u8)
            mval = ((const uint8_t*)mask)[(size_t)bs * J_ + j];
        else
            mval = ((const int*)mask)[(size_t)bs * J_ + j];
    }

    float4 qv[4];
    {
        const float4* q4 = reinterpret_cast<const float4*>(g_qt + b * IDIM_);
        #pragma unroll
        for (int k = 0; k < 4; ++k) qv[k] = q4[lane + 32 * k];
    }

    const unsigned sbase = (unsigned)__cvta_generic_to_shared(&s_stage[0][0]);
    const unsigned BUFB  = (unsigned)(CHK_ * 128 * 16);

    // Prologue: issue chunks 0 and 1
    #pragma unroll
    for (int u = 0; u < 4; ++u)
        cp_async16(sbase + (unsigned)(tid + 256 * u) * 16u, x4 + tid + 256 * u);
    cp_commit();
    #pragma unroll
    for (int u = 0; u < 4; ++u)
        cp_async16(sbase + BUFB + (unsigned)(tid + 256 * u) * 16u,
                   x4 + CHK_ * 128 + tid + 256 * u);
    cp_commit();

    float m = -1e30f, d = 0.f;
    float4 p[4];
    #pragma unroll
    for (int k = 0; k < 4; ++k) p[k] = make_float4(0.f, 0.f, 0.f, 0.f);

    int cur = 0, nxt2 = 2;

    for (int c = 0; c < NCHK_; ++c) {
        if (c == NCHK_ - 1) cp_wait0(); else cp_wait1();   // chunk c landed
        __syncthreads();   // visible to all; chunk c-1 fully consumed

        if (c + 2 < NCHK_) {
            const unsigned sb = sbase + (unsigned)nxt2 * BUFB;
            const float4* src = x4 + (size_t)(c + 2) * (CHK_ * 128);
            #pragma unroll
            for (int u = 0; u < 4; ++u)
                cp_async16(sb + (unsigned)(tid + 256 * u) * 16u, src + tid + 256 * u);
            cp_commit();
        }

        // Warp w processes row w of this chunk: load once, use twice.
        const float4* r0 = &s_stage[cur][wid * 128];
        float4 xv[4];
        #pragma unroll
        for (int k = 0; k < 4; ++k) xv[k] = r0[lane + 32 * k];

        float s = 0.f;
        #pragma unroll
        for (int k = 0; k < 4; ++k) {
            s = fmaf(xv[k].x, qv[k].x, s);
            s = fmaf(xv[k].y, qv[k].y, s);
            s = fmaf(xv[k].z, qv[k].z, s);
            s = fmaf(xv[k].w, qv[k].w, s);
        }
        #pragma unroll
        for (int off = 16; off > 0; off >>= 1)
            s += __shfl_xor_sync(0xffffffffu, s, off);

        if (__shfl_sync(0xffffffffu, mval, c) != 0) s = -1e30f;

        const float mn = fmaxf(m, s);
        const float f  = __expf(m - mn);
        const float w  = __expf(s - mn);
        m = mn;
        d = fmaf(d, f, w);
        #pragma unroll
        for (int k = 0; k < 4; ++k) {
            p[k].x = fmaf(p[k].x, f, w * xv[k].x);
            p[k].y = fmaf(p[k].y, f, w * xv[k].y);
            p[k].z = fmaf(p[k].z, f, w * xv[k].z);
            p[k].w = fmaf(p[k].w, f, w * xv[k].w);
        }

        cur  = (cur == 2)  ? 0 : cur + 1;
        nxt2 = (nxt2 == 2) ? 0 : nxt2 + 1;
    }

    // ---- merge 8 per-warp states (reuse staging smem: 8 x 512 floats) ----
    __syncthreads();   // all warps done with final chunk; staging free
    if (lane == 0) { s_m[wid] = m; s_d[wid] = d; }
    {
        float4* mp = reinterpret_cast<float4*>(&s_stage[0][0]);
        #pragma unroll
        for (int k = 0; k < 4; ++k) mp[wid * 128 + lane + 32 * k] = p[k];
    }
    __syncthreads();

    float M = -1e30f;
    #pragma unroll
    for (int w = 0; w < 8; ++w) M = fmaxf(M, s_m[w]);
    float coef[8];
    float D = 0.f;
    #pragma unroll
    for (int w = 0; w < 8; ++w) {
        coef[w] = __expf(s_m[w] - M);
        D = fmaf(s_d[w], coef[w], D);
    }
    const float inv = 1.f / D;

    // thread owns cols {2*tid, 2*tid+1}
    const float2* mp2 = reinterpret_cast<const float2*>(&s_stage[0][0]);
    float ox = 0.f, oy = 0.f;
    #pragma unroll
    for (int w = 0; w < 8; ++w) {
        const float2 v = mp2[w * 256 + tid];
        ox = fmaf(v.x, coef[w], ox);
        oy = fmaf(v.y, coef[w], oy);
    }
    reinterpret_cast<float2*>(g_pooled + (size_t)bs * IDIM_)[tid] =
        make_float2(ox * inv, oy * inv);
}

// ---------------------------------------------------------------------------
// Kernel 3: cp.async double-buffered GEMM (identical to R12)
// out[1024,256] = pooled[1024,512] @ WvT[512,256]
// BM=32, BN=64, BK=32; 256 threads, 2x4 register tile; 128 blocks.
// ---------------------------------------------------------------------------
#define BM_ 32
#define BN_ 64
#define BK_ 32
#define SAP_ 36
__global__ __launch_bounds__(256) void epilogue_kernel(float* __restrict__ out)
{
    const int tid = threadIdx.x;
    const int h0  = blockIdx.x * BN_;
    const int m0  = blockIdx.y * BM_;
    const int tx  = tid & 15;
    const int ty  = tid >> 4;

    __shared__ __align__(16) float sA[2][BM_][SAP_];
    __shared__ __align__(16) float sB[2][BK_][BN_];

    float acc[2][4];
    #pragma unroll
    for (int i = 0; i < 2; ++i)
        #pragma unroll
        for (int j = 0; j < 4; ++j) acc[i][j] = 0.f;

    const int ar = tid >> 3;
    const int ac = (tid & 7) * 4;
    const int br = tid >> 4;
    const int bc = (tid & 15) * 4;

    const unsigned sAu = (unsigned)__cvta_generic_to_shared(&sA[0][0][0]);
    const unsigned sBu = (unsigned)__cvta_generic_to_shared(&sB[0][0][0]);
    const unsigned ABUF = (unsigned)(BM_ * SAP_ * 4);
    const unsigned BBUF = (unsigned)(BK_ * BN_ * 4);

    {
        cp_async16(sAu + (unsigned)(ar * SAP_ + ac) * 4u,
                   g_pooled + (size_t)(m0 + ar) * IDIM_ + ac);
        #pragma unroll
        for (int r = 0; r < 2; ++r) {
            const int kk = br + 16 * r;
            cp_async16(sBu + (unsigned)(kk * BN_ + bc) * 4u,
                       g_WvT + (size_t)kk * HDIM_ + h0 + bc);
        }
        cp_commit();
    }

    const int NCH = IDIM_ / BK_;   // 16
    for (int c = 0; c < NCH; ++c) {
        const int cur = c & 1;

        if (c + 1 < NCH) {
            const int k0 = (c + 1) * BK_;
            const unsigned oa = sAu + (unsigned)(cur ^ 1) * ABUF;
            const unsigned ob = sBu + (unsigned)(cur ^ 1) * BBUF;
            cp_async16(oa + (unsigned)(ar * SAP_ + ac) * 4u,
                       g_pooled + (size_t)(m0 + ar) * IDIM_ + k0 + ac);
            #pragma unroll
            for (int r = 0; r < 2; ++r) {
                const int kk = br + 16 * r;
                cp_async16(ob + (unsigned)(kk * BN_ + bc) * 4u,
                           g_WvT + (size_t)(k0 + kk) * HDIM_ + h0 + bc);
            }
            cp_commit();
        }

        if (c + 1 < NCH) cp_wait1(); else cp_wait0();
        __syncthreads();

        #pragma unroll
        for (int kk = 0; kk < BK_; ++kk) {
            const float a0 = sA[cur][ty * 2 + 0][kk];
            const float a1 = sA[cur][ty * 2 + 1][kk];
            const float4 bv = *reinterpret_cast<const float4*>(&sB[cur][kk][tx * 4]);
            acc[0][0] = fmaf(a0, bv.x, acc[0][0]);
            acc[0][1] = fmaf(a0, bv.y, acc[0][1]);
            acc[0][2] = fmaf(a0, bv.z, acc[0][2]);
            acc[0][3] = fmaf(a0, bv.w, acc[0][3]);
            acc[1][0] = fmaf(a1, bv.x, acc[1][0]);
            acc[1][1] = fmaf(a1, bv.y, acc[1][1]);
            acc[1][2] = fmaf(a1, bv.z, acc[1][2]);
            acc[1][3] = fmaf(a1, bv.w, acc[1][3]);
        }
        __syncthreads();
    }

    #pragma unroll
    for (int i = 0; i < 2; ++i) {
        const float4 v = make_float4(acc[i][0], acc[i][1], acc[i][2], acc[i][3]);
        *reinterpret_cast<float4*>(
            out + (size_t)(m0 + ty * 2 + i) * HDIM_ + h0 + tx * 4) = v;
    }
}

// ---------------------------------------------------------------------------
// Launch.  Inputs: query, other_semesters, mask, Wq, Wk, Wv
// ---------------------------------------------------------------------------
extern "C" void kernel_launch(void* const* d_in, const int* in_sizes, int n_in,
                              void* d_out, int out_size)
{
    const float* query = (const float*)d_in[0];
    const float* X     = (const float*)d_in[1];
    const void*  mask  = d_in[2];
    const float* Wq    = (const float*)d_in[3];
    const float* Wk    = (const float*)d_in[4];
    const float* Wv    = (const float*)d_in[5];
    float*       out   = (float*)d_out;

    prologue_kernel<<<192, 256>>>(query, Wq, Wv, (const unsigned*)mask);
    qt_kernel<<<256, 256>>>(Wk);
    flash_pool_kernel<<<BS_, 256>>>(X, mask);
    epilogue_kernel<<<dim3(HDIM_ / BN_, BS_ / BM_), 256>>>(out);
}